// round 14
// baseline (speedup 1.0000x reference)
#include <cuda_runtime.h>
#include <cuda_fp16.h>
#include <math.h>
#include <stdint.h>

#define M_ROWS 100352   // 32 * 3136 = 2048 windows * 49
#define CDIM   192
#define HIDDEN 768
#define QKV3   576

// GEMM tiling: block 128x96, 4 warps of 64x48 (2M x 2N), 3-stage cp.async, fp16
#define TM 128
#define TN 96
#define NSTAGE 3
#define A_PITCH 40                    // halves per A row: 80B pitch -> ldmatrix conflict-free
#define B_PITCH 104                   // half2 per B k-pair row (96+8): bank = (8tq+g)%32, distinct
#define ASZ_H  (TM * A_PITCH)         // 5120 halves / stage
#define BSZ_H2 (16 * B_PITCH)         // 1664 half2 / stage
#define STAGE_BYTES (ASZ_H * 2 + BSZ_H2 * 4)   // 16896
#define SMEM_SZ (NSTAGE * STAGE_BYTES)         // 50688

// ---------------- scratch (no allocs allowed) ----------------
__device__ __align__(16) __half  g_xw  [(size_t)M_ROWS * CDIM];
__device__ __align__(16) __half  g_qkv [(size_t)M_ROWS * QKV3];
__device__ __align__(16) __half  g_attn[(size_t)M_ROWS * CDIM];
__device__ __align__(16) __half  g_y   [(size_t)M_ROWS * CDIM];
__device__ __align__(16) __half  g_h   [(size_t)M_ROWS * HIDDEN];
// fp16 weights, k-pair interleaved half2: w16[(k/2)*N + n] = (w[k][n], w[k+1][n])
#define W_QKV  0
#define W_PROJ 55296
#define W_FC1  73728
#define W_FC2  147456
#define W_TOT  221184
__device__ __align__(16) __half2 g_w16[W_TOT];
// combined rel-pos bias + shift mask: [cls][head][i*49+j], cls = (wy==7)*2 | (wx==7)
#define BTAB_N (4 * 6 * 2401)
__device__ float g_btab[BTAB_N];

// ---------------- helpers ----------------
__device__ __forceinline__ uint32_t smem_u32(const void* p) {
    uint32_t a;
    asm("{ .reg .u64 t; cvta.to.shared.u64 t, %1; cvt.u32.u64 %0, t; }" : "=r"(a) : "l"(p));
    return a;
}
__device__ __forceinline__ void cpa16(uint32_t dst, const void* src) {
    asm volatile("cp.async.cg.shared.global [%0], [%1], 16;" :: "r"(dst), "l"(src));
}
#define CP_COMMIT() asm volatile("cp.async.commit_group;" ::: "memory")
#define CP_WAIT1()  asm volatile("cp.async.wait_group 1;" ::: "memory")
#define CP_WAIT0()  asm volatile("cp.async.wait_group 0;" ::: "memory")

__device__ __forceinline__ void mma_f16(float c[4], const unsigned a[4], const unsigned b[2]) {
    asm volatile(
        "mma.sync.aligned.m16n8k16.row.col.f32.f16.f16.f32 "
        "{%0,%1,%2,%3}, {%4,%5,%6,%7}, {%8,%9}, {%0,%1,%2,%3};"
        : "+f"(c[0]), "+f"(c[1]), "+f"(c[2]), "+f"(c[3])
        : "r"(a[0]), "r"(a[1]), "r"(a[2]), "r"(a[3]), "r"(b[0]), "r"(b[1]));
}
__device__ __forceinline__ void ldsm_x4(unsigned r[4], uint32_t addr) {
    asm volatile("ldmatrix.sync.aligned.m8n8.x4.shared.b16 {%0,%1,%2,%3}, [%4];"
        : "=r"(r[0]), "=r"(r[1]), "=r"(r[2]), "=r"(r[3]) : "r"(addr));
}
__device__ __forceinline__ unsigned pack_h2(float a, float b) {
    __half2 h = __floats2half2_rn(a, b);
    return *(unsigned*)&h;
}

// window-layout row -> token index (cyclic shift by +3 both axes)
__device__ __forceinline__ size_t win_row_to_token(int r) {
    int win = r / 49;
    int n   = r - win * 49;
    int b   = win >> 6;
    int wi  = win & 63;
    int ri  = n / 7;
    int ci  = n - ri * 7;
    int hs = (wi >> 3) * 7 + ri + 3; if (hs >= 56) hs -= 56;
    int ws = (wi & 7)  * 7 + ci + 3; if (ws >= 56) ws -= 56;
    return (size_t)b * 3136 + (size_t)hs * 56 + ws;
}

// ---------------- all-weights fp32 -> interleaved fp16 (single launch) ----------------
__global__ __launch_bounds__(256)
void w2h_all(const float* __restrict__ qkv_w, const float* __restrict__ proj_w,
             const float* __restrict__ fc1_w, const float* __restrict__ fc2_w,
             __half2* __restrict__ out) {
    int i = blockIdx.x * 256 + threadIdx.x;
    if (i >= W_TOT) return;
    const float* w; int N, base;
    if      (i < W_PROJ) { w = qkv_w;  N = QKV3;   base = W_QKV;  }
    else if (i < W_FC1)  { w = proj_w; N = CDIM;   base = W_PROJ; }
    else if (i < W_FC2)  { w = fc1_w;  N = HIDDEN; base = W_FC1;  }
    else                 { w = fc2_w;  N = CDIM;   base = W_FC2;  }
    int j = i - base;
    int kq = j / N, n = j - kq * N;
    out[i] = __halves2half2(__float2half(w[(size_t)(2 * kq) * N + n]),
                            __float2half(w[(size_t)(2 * kq + 1) * N + n]));
}

// ---------------- bias+mask table precompute ----------------
__global__ __launch_bounds__(256)
void bias_tbl(const float* __restrict__ rpb, float* __restrict__ tbl) {
    int idx = blockIdx.x * 256 + threadIdx.x;
    if (idx >= BTAB_N) return;
    int cls  = idx / (6 * 2401);
    int rem  = idx - cls * 6 * 2401;
    int head = rem / 2401;
    int e    = rem - head * 2401;
    int i = e / 49, j = e - i * 49;
    int yi = i / 7, xi = i - yi * 7;
    int yj = j / 7, xj = j - yj * 7;
    float v = rpb[((yi - yj + 6) * 13 + (xi - xj + 6)) * 6 + head];
    bool wy7 = (cls & 2) != 0, wx7 = (cls & 1) != 0;
    int gri = wy7 ? (yi < 4 ? 1 : 2) : 0;
    int gci = wx7 ? (xi < 4 ? 1 : 2) : 0;
    int grj = wy7 ? (yj < 4 ? 1 : 2) : 0;
    int gcj = wx7 ? (xj < 4 ? 1 : 2) : 0;
    if (gri * 3 + gci != grj * 3 + gcj) v -= 100.f;
    tbl[idx] = v;
}

// ---------------- LayerNorm (1 warp per row), fp16 output ----------------
template<bool GATHER>
__global__ __launch_bounds__(256)
void ln_kernel(const float* __restrict__ in, const float* __restrict__ gamma,
               const float* __restrict__ beta, __half* __restrict__ out) {
    int row  = blockIdx.x * 8 + (threadIdx.x >> 5);
    int lane = threadIdx.x & 31;
    size_t t = GATHER ? win_row_to_token(row) : (size_t)row;
    const float* p = in + t * CDIM;
    float v[6];
    float s = 0.f, ss = 0.f;
#pragma unroll
    for (int i = 0; i < 6; i++) {
        v[i] = p[lane + 32 * i];
        s  += v[i];
        ss += v[i] * v[i];
    }
#pragma unroll
    for (int o = 16; o; o >>= 1) {
        s  += __shfl_xor_sync(0xffffffffu, s, o);
        ss += __shfl_xor_sync(0xffffffffu, ss, o);
    }
    float mu   = s * (1.f / CDIM);
    float var  = ss * (1.f / CDIM) - mu * mu;
    float rinv = rsqrtf(var + 1e-5f);
    __half* q = out + (size_t)row * CDIM;
#pragma unroll
    for (int i = 0; i < 6; i++) {
        int c = lane + 32 * i;
        q[c] = __float2half((v[i] - mu) * rinv * gamma[c] + beta[c]);
    }
}

// ---------------- fp16 mma.sync GEMM, cp.async 3-stage, ldmatrix A, fused epilogues ----
// MODE 0: Ch = A@B + bias                      (qkv, fp16 out)
// MODE 1: d_out[token] = x[token] + A@B + bias (proj + window-reverse + residual, fp32)
// MODE 2: Ch = gelu(A@B + bias)                (fc1, fp16 out)
// MODE 3: Cf += A@B + bias                     (fc2 + residual into d_out, fp32)
template<int MODE>
__global__ __launch_bounds__(128, 3)
void gemm_f16(const __half* __restrict__ A, const __half2* __restrict__ Bw,
              const float* __restrict__ bias, void* __restrict__ Cv,
              const float* __restrict__ extra, int K, int N) {
    extern __shared__ __align__(16) char smem[];

    const int tid  = threadIdx.x;
    const int warp = tid >> 5;
    const int lane = tid & 31;
    const int row0 = blockIdx.y * TM;
    const int col0 = blockIdx.x * TN;
    const int wm = (warp & 1) * 64;
    const int wn = (warp >> 1) * 48;
    const int g  = lane >> 2;
    const int tq = lane & 3;
    const int nk = K >> 5;
    const uint32_t sm_u = smem_u32(smem);
    const uint32_t lm_lane = (uint32_t)(((wm + (lane & 15)) * A_PITCH + ((lane >> 4) * 8)) * 2);

    auto issue = [&](int kb, int s) {
        uint32_t st = sm_u + (uint32_t)s * STAGE_BYTES;
        const __half* Abase = A + (size_t)row0 * K + kb * 32;
#pragma unroll
        for (int u = 0; u < 4; u++) {
            int idx = tid + u * 128;            // 0..511: m = idx/4, chunk c = idx%4 (8 halves)
            int m = idx >> 2, c = idx & 3;
            cpa16(st + (uint32_t)(m * A_PITCH + c * 8) * 2, Abase + (size_t)m * K + c * 8);
        }
        uint32_t bt = st + ASZ_H * 2;
        const __half2* Bbase = Bw + (size_t)(kb * 16) * N + col0;
#pragma unroll
        for (int u = 0; u < 3; u++) {
            int idx = tid + u * 128;            // 0..383: kq = idx/24, chunk c = idx%24 (4 half2)
            int kq = idx / 24, c = idx - kq * 24;
            cpa16(bt + (uint32_t)(kq * B_PITCH + c * 4) * 4, Bbase + (size_t)kq * N + c * 4);
        }
    };

    float acc[4][6][4];
#pragma unroll
    for (int mi = 0; mi < 4; mi++)
#pragma unroll
        for (int ni = 0; ni < 6; ni++)
#pragma unroll
            for (int j = 0; j < 4; j++) acc[mi][ni][j] = 0.f;

    issue(0, 0); CP_COMMIT();
    issue(1, 1); CP_COMMIT();

    for (int kb = 0; kb < nk; kb++) {
        if (kb + 2 < nk) { CP_WAIT1(); } else { CP_WAIT0(); }
        __syncthreads();
        int s = kb % NSTAGE;
        if (kb + 2 < nk) { issue(kb + 2, (kb + 2) % NSTAGE); CP_COMMIT(); }

        uint32_t a_u = sm_u + (uint32_t)s * STAGE_BYTES + lm_lane;
        const __half2* b = (const __half2*)(smem + (size_t)s * STAGE_BYTES + ASZ_H * 2);
#pragma unroll
        for (int ks = 0; ks < 2; ks++) {
            unsigned af[4][4], bf[6][2];
#pragma unroll
            for (int mi = 0; mi < 4; mi++)
                ldsm_x4(af[mi], a_u + (uint32_t)((mi * 16 * A_PITCH + ks * 16) * 2));
#pragma unroll
            for (int ni = 0; ni < 6; ni++) {
                int n0 = wn + ni * 8;
                bf[ni][0] = *(const unsigned*)(b + (ks * 8 + tq)     * B_PITCH + n0 + g);
                bf[ni][1] = *(const unsigned*)(b + (ks * 8 + tq + 4) * B_PITCH + n0 + g);
            }
#pragma unroll
            for (int mi = 0; mi < 4; mi++)
#pragma unroll
                for (int ni = 0; ni < 6; ni++)
                    mma_f16(acc[mi][ni], af[mi], bf[ni]);
        }
        __syncthreads();
    }

    float* Cf = (float*)Cv;
    __half* Ch = (__half*)Cv;
#pragma unroll
    for (int mi = 0; mi < 4; mi++) {
#pragma unroll
        for (int h = 0; h < 2; h++) {
            int r = row0 + wm + mi * 16 + g + h * 8;
            float* dstf = nullptr;
            const float* xrow = nullptr;
            if (MODE == 1) {
                size_t t = win_row_to_token(r);
                dstf = Cf + t * CDIM;
                xrow = extra + t * CDIM;
            } else if (MODE == 3) {
                dstf = Cf + (size_t)r * N;
            }
#pragma unroll
            for (int ni = 0; ni < 6; ni++) {
                int c = col0 + wn + ni * 8 + tq * 2;
                float ox = acc[mi][ni][h * 2 + 0] + bias[c];
                float oy = acc[mi][ni][h * 2 + 1] + bias[c + 1];
                if (MODE == 0) {
                    *(__half2*)(Ch + (size_t)r * N + c) =
                        __halves2half2(__float2half(ox), __float2half(oy));
                } else if (MODE == 1) {
                    float2 xv = *(const float2*)(xrow + c);
                    float2 o = {ox + xv.x, oy + xv.y};
                    *(float2*)(dstf + c) = o;
                } else if (MODE == 2) {
                    ox = 0.5f * ox * (1.f + erff(ox * 0.70710678118654752f));
                    oy = 0.5f * oy * (1.f + erff(oy * 0.70710678118654752f));
                    *(__half2*)(Ch + (size_t)r * N + c) =
                        __halves2half2(__float2half(ox), __float2half(oy));
                } else {
                    float2 cv = *(const float2*)(dstf + c);
                    float2 o = {ox + cv.x, oy + cv.y};
                    *(float2*)(dstf + c) = o;
                }
            }
        }
    }
}

// ---------------- tensor-core windowed attention: 1 block per (window, head) ----------
// Q,K padded 49->64; softmax fully in registers; P reused as mma A-fragments.
// bias+mask from precomputed table (SMEM-resident).
#define QK_PITCH 40     // halves per Q/K row
#define VT_PITCH 72     // halves per Vt row
__global__ __launch_bounds__(128)
void attn_tc(const __half* __restrict__ qkv, const float* __restrict__ btab,
             __half* __restrict__ outp) {
    __shared__ __align__(16) __half sQ[64 * QK_PITCH];    // 320 uint4
    __shared__ __align__(16) __half sK[64 * QK_PITCH];    // 320 uint4
    __shared__ __align__(16) __half sVt[32 * VT_PITCH];   // 288 uint4
    __shared__ float sT[2401];

    const int blk = blockIdx.x;
    const int win = blk / 6, head = blk % 6;
    const int tid = threadIdx.x, warp = tid >> 5, lane = tid & 31;
    const int g = lane >> 2, tq = lane & 3;

    // zero all tiles (padding rows/cols must be 0)
    {
        uint4 z4 = {0, 0, 0, 0};
        uint4* zq = (uint4*)sQ;
        uint4* zk = (uint4*)sK;
        uint4* zv = (uint4*)sVt;
#pragma unroll
        for (int u = 0; u < 2; u++) { zq[tid + u * 128] = z4; zk[tid + u * 128] = z4; zv[tid + u * 128] = z4; }
        if (tid < 64) { zq[tid + 256] = z4; zk[tid + 256] = z4; }
        if (tid < 32) zv[tid + 256] = z4;
    }
    // bias+mask table slice
    const int wi = win & 63;
    const int wy = wi >> 3, wx = wi & 7;
    const int cls = ((wy == 7) ? 2 : 0) | ((wx == 7) ? 1 : 0);
    const float* tb = btab + (size_t)(cls * 6 + head) * 2401;
    for (int t = tid; t < 2401; t += 128) sT[t] = tb[t];

    const __half* base = qkv + (size_t)win * 49 * QKV3 + head * 32;
    // Q, K: 49 rows x 4 chunks of 8 halves
    for (int t = tid; t < 49 * 4; t += 128) {
        int n = t >> 2, c = t & 3;
        *(uint4*)(sQ + n * QK_PITCH + c * 8) = *(const uint4*)(base + (size_t)n * QKV3 + c * 8);
        *(uint4*)(sK + n * QK_PITCH + c * 8) = *(const uint4*)(base + (size_t)n * QKV3 + 192 + c * 8);
    }
    // V transpose: V[j][d] -> Vt[d][j]
    for (int t = tid; t < 49 * 16; t += 128) {
        int j = t >> 4, dp = t & 15;
        __half2 h = *(const __half2*)(base + (size_t)j * QKV3 + 384 + dp * 2);
        sVt[(dp * 2)     * VT_PITCH + j] = __low2half(h);
        sVt[(dp * 2 + 1) * VT_PITCH + j] = __high2half(h);
    }
    __syncthreads();

    // ---- QK^T: per warp rows wm..wm+15 ----
    const int wm = warp * 16;
    unsigned aq[2][4];
    {
        uint32_t a_u = smem_u32(sQ) + (uint32_t)(((wm + (lane & 15)) * QK_PITCH + (lane >> 4) * 8) * 2);
        ldsm_x4(aq[0], a_u);
        ldsm_x4(aq[1], a_u + 32);
    }
    float sc[8][4];
#pragma unroll
    for (int nt = 0; nt < 8; nt++) {
        sc[nt][0] = sc[nt][1] = sc[nt][2] = sc[nt][3] = 0.f;
        const __half* kr = sK + (nt * 8 + g) * QK_PITCH + tq * 2;
        unsigned bfa[2] = { *(const unsigned*)kr,        *(const unsigned*)(kr + 8)  };
        unsigned bfb[2] = { *(const unsigned*)(kr + 16), *(const unsigned*)(kr + 24) };
        mma_f16(sc[nt], aq[0], bfa);
        mma_f16(sc[nt], aq[1], bfb);
    }

    // ---- softmax in registers (table supplies bias+mask) ----
    int ib[2];
    bool rowok[2];
#pragma unroll
    for (int r = 0; r < 2; r++) {
        int i = wm + g + r * 8;
        rowok[r] = (i < 49);
        ib[r] = (rowok[r] ? i : 0) * 49;
    }
    float vmax[2] = {-1e30f, -1e30f};
#pragma unroll
    for (int nt = 0; nt < 8; nt++) {
#pragma unroll
        for (int c = 0; c < 4; c++) {
            int j = nt * 8 + tq * 2 + (c & 1);
            int r = c >> 1;
            float v;
            if (j < 49 && rowok[r]) {
                v = fmaf(sc[nt][c], 0.17677669529663687f, sT[ib[r] + j]);
            } else {
                v = -1e30f;
            }
            sc[nt][c] = v;
            vmax[r] = fmaxf(vmax[r], v);
        }
    }
#pragma unroll
    for (int r = 0; r < 2; r++) {
        vmax[r] = fmaxf(vmax[r], __shfl_xor_sync(0xffffffffu, vmax[r], 1));
        vmax[r] = fmaxf(vmax[r], __shfl_xor_sync(0xffffffffu, vmax[r], 2));
    }
    float vsum[2] = {0.f, 0.f};
#pragma unroll
    for (int nt = 0; nt < 8; nt++) {
#pragma unroll
        for (int c = 0; c < 4; c++) {
            int r = c >> 1;
            float e = __expf(sc[nt][c] - vmax[r]);
            sc[nt][c] = e;
            vsum[r] += e;
        }
    }
#pragma unroll
    for (int r = 0; r < 2; r++) {
        vsum[r] += __shfl_xor_sync(0xffffffffu, vsum[r], 1);
        vsum[r] += __shfl_xor_sync(0xffffffffu, vsum[r], 2);
    }
    float inv0 = 1.f / vsum[0], inv1 = 1.f / vsum[1];

    // ---- P as A-fragments, PV ----
    unsigned ap[4][4];
#pragma unroll
    for (int kc = 0; kc < 4; kc++) {
        ap[kc][0] = pack_h2(sc[2 * kc][0],     sc[2 * kc][1]);
        ap[kc][1] = pack_h2(sc[2 * kc][2],     sc[2 * kc][3]);
        ap[kc][2] = pack_h2(sc[2 * kc + 1][0], sc[2 * kc + 1][1]);
        ap[kc][3] = pack_h2(sc[2 * kc + 1][2], sc[2 * kc + 1][3]);
    }
    float oacc[4][4];
#pragma unroll
    for (int dt = 0; dt < 4; dt++) {
        oacc[dt][0] = oacc[dt][1] = oacc[dt][2] = oacc[dt][3] = 0.f;
#pragma unroll
        for (int kc = 0; kc < 4; kc++) {
            const __half* vr = sVt + (dt * 8 + g) * VT_PITCH + kc * 16 + tq * 2;
            unsigned bf[2] = { *(const unsigned*)vr, *(const unsigned*)(vr + 8) };
            mma_f16(oacc[dt], ap[kc], bf);
        }
    }

    // ---- store ----
#pragma unroll
    for (int r = 0; r < 2; r++) {
        int i = wm + g + r * 8;
        if (i < 49) {
            float invr = r ? inv1 : inv0;
            __half* dst = outp + ((size_t)win * 49 + i) * CDIM + head * 32;
#pragma unroll
            for (int dt = 0; dt < 4; dt++) {
                float ox = oacc[dt][r * 2 + 0] * invr;
                float oy = oacc[dt][r * 2 + 1] * invr;
                *(__half2*)(dst + dt * 8 + tq * 2) = __floats2half2_rn(ox, oy);
            }
        }
    }
}

// ---------------- launch ----------------
extern "C" void kernel_launch(void* const* d_in, const int* in_sizes, int n_in,
                              void* d_out, int out_size) {
    const float* x      = (const float*)d_in[0];
    const float* n1g    = (const float*)d_in[1];
    const float* n1b    = (const float*)d_in[2];
    const float* qkv_w  = (const float*)d_in[3];
    const float* qkv_b  = (const float*)d_in[4];
    const float* rpb    = (const float*)d_in[5];
    const float* proj_w = (const float*)d_in[6];
    const float* proj_b = (const float*)d_in[7];
    const float* n2g    = (const float*)d_in[8];
    const float* n2b    = (const float*)d_in[9];
    const float* fc1_w  = (const float*)d_in[10];
    const float* fc1_b  = (const float*)d_in[11];
    const float* fc2_w  = (const float*)d_in[12];
    const float* fc2_b  = (const float*)d_in[13];
    float* out = (float*)d_out;

    __half *p_xw, *p_qkv, *p_attn, *p_y, *p_h;
    __half2 *p_w16;
    float *p_btab;
    cudaGetSymbolAddress((void**)&p_xw,   g_xw);
    cudaGetSymbolAddress((void**)&p_qkv,  g_qkv);
    cudaGetSymbolAddress((void**)&p_attn, g_attn);
    cudaGetSymbolAddress((void**)&p_y,    g_y);
    cudaGetSymbolAddress((void**)&p_h,    g_h);
    cudaGetSymbolAddress((void**)&p_w16,  g_w16);
    cudaGetSymbolAddress((void**)&p_btab, g_btab);

    cudaFuncSetAttribute(gemm_f16<0>, cudaFuncAttributeMaxDynamicSharedMemorySize, SMEM_SZ);
    cudaFuncSetAttribute(gemm_f16<1>, cudaFuncAttributeMaxDynamicSharedMemorySize, SMEM_SZ);
    cudaFuncSetAttribute(gemm_f16<2>, cudaFuncAttributeMaxDynamicSharedMemorySize, SMEM_SZ);
    cudaFuncSetAttribute(gemm_f16<3>, cudaFuncAttributeMaxDynamicSharedMemorySize, SMEM_SZ);

    const int MT = M_ROWS / TM;   // 784

    // 0. weight conversion + bias table
    w2h_all<<<(W_TOT + 255) / 256, 256>>>(qkv_w, proj_w, fc1_w, fc2_w, p_w16);
    bias_tbl<<<(BTAB_N + 255) / 256, 256>>>(rpb, p_btab);

    // 1. LN1 + shift + window partition (fp16 out)
    ln_kernel<true><<<M_ROWS / 8, 256>>>(x, n1g, n1b, p_xw);
    // 2. QKV projection (fp16 out)
    gemm_f16<0><<<dim3(QKV3 / TN, MT), 128, SMEM_SZ>>>(p_xw, p_w16 + W_QKV, qkv_b, p_qkv, nullptr, CDIM, QKV3);
    // 3. tensor-core windowed attention (fp16 in/out)
    attn_tc<<<2048 * 6, 128>>>(p_qkv, p_btab, p_attn);
    // 4. proj + window reverse + un-shift + residual -> d_out holds x1 (fp32)
    gemm_f16<1><<<dim3(CDIM / TN, MT), 128, SMEM_SZ>>>(p_attn, p_w16 + W_PROJ, proj_b, out, x, CDIM, CDIM);
    // 5. LN2 (fp16 out)
    ln_kernel<false><<<M_ROWS / 8, 256>>>(out, n2g, n2b, p_y);
    // 6. FC1 + GELU (fp16 out)
    gemm_f16<2><<<dim3(HIDDEN / TN, MT), 128, SMEM_SZ>>>(p_y, p_w16 + W_FC1, fc1_b, p_h, nullptr, CDIM, HIDDEN);
    // 7. FC2 + residual add into d_out (fp32)
    gemm_f16<3><<<dim3(CDIM / TN, MT), 128, SMEM_SZ>>>(p_h, p_w16 + W_FC2, fc2_b, out, nullptr, HIDDEN, CDIM);
}

// round 15
// speedup vs baseline: 1.1014x; 1.1014x over previous
#include <cuda_runtime.h>
#include <cuda_fp16.h>
#include <math.h>
#include <stdint.h>

#define M_ROWS 100352   // 32 * 3136 = 2048 windows * 49
#define CDIM   192
#define HIDDEN 768
#define QKV3   576

// GEMM tiling: block 128x64, 4 warps of 64x32, 3-stage cp.async, fp16 operands
#define TM 128
#define TN 64
#define NSTAGE 3
#define A_PITCH 40                    // halves per A row: 80B pitch -> ldmatrix conflict-free
#define B_PITCH 72                    // half2 per B k-pair row: bank = (8tq+g)%32, distinct
#define ASZ_H  (TM * A_PITCH)         // 5120 halves / stage
#define BSZ_H2 (16 * B_PITCH)         // 1152 half2 / stage
#define STAGE_BYTES (ASZ_H * 2 + BSZ_H2 * 4)   // 14848
#define SMEM_SZ (NSTAGE * STAGE_BYTES)         // 44544

// ---------------- scratch (no allocs allowed) ----------------
__device__ __align__(16) __half  g_xw  [(size_t)M_ROWS * CDIM];
__device__ __align__(16) __half  g_qkv [(size_t)M_ROWS * QKV3];
__device__ __align__(16) __half  g_attn[(size_t)M_ROWS * CDIM];
__device__ __align__(16) __half  g_y   [(size_t)M_ROWS * CDIM];
__device__ __align__(16) __half  g_h   [(size_t)M_ROWS * HIDDEN];
// fp16 weights, k-pair interleaved half2: w16[(k/2)*N + n] = (w[k][n], w[k+1][n])
#define W_QKV  0
#define W_PROJ 55296
#define W_FC1  73728
#define W_FC2  147456
#define W_TOT  221184
__device__ __align__(16) __half2 g_w16[W_TOT];
// combined rel-pos bias + shift mask: [cls][head][i*49+j], cls = (wy==7)*2 | (wx==7)
#define BTAB_N (4 * 6 * 2401)
__device__ float g_btab[BTAB_N];

// ---------------- helpers ----------------
__device__ __forceinline__ uint32_t smem_u32(const void* p) {
    uint32_t a;
    asm("{ .reg .u64 t; cvta.to.shared.u64 t, %1; cvt.u32.u64 %0, t; }" : "=r"(a) : "l"(p));
    return a;
}
__device__ __forceinline__ void cpa16(uint32_t dst, const void* src) {
    asm volatile("cp.async.cg.shared.global [%0], [%1], 16;" :: "r"(dst), "l"(src));
}
#define CP_COMMIT() asm volatile("cp.async.commit_group;" ::: "memory")
#define CP_WAIT1()  asm volatile("cp.async.wait_group 1;" ::: "memory")
#define CP_WAIT0()  asm volatile("cp.async.wait_group 0;" ::: "memory")

__device__ __forceinline__ void mma_f16(float c[4], const unsigned a[4], const unsigned b[2]) {
    asm volatile(
        "mma.sync.aligned.m16n8k16.row.col.f32.f16.f16.f32 "
        "{%0,%1,%2,%3}, {%4,%5,%6,%7}, {%8,%9}, {%0,%1,%2,%3};"
        : "+f"(c[0]), "+f"(c[1]), "+f"(c[2]), "+f"(c[3])
        : "r"(a[0]), "r"(a[1]), "r"(a[2]), "r"(a[3]), "r"(b[0]), "r"(b[1]));
}
__device__ __forceinline__ void ldsm_x4(unsigned r[4], uint32_t addr) {
    asm volatile("ldmatrix.sync.aligned.m8n8.x4.shared.b16 {%0,%1,%2,%3}, [%4];"
        : "=r"(r[0]), "=r"(r[1]), "=r"(r[2]), "=r"(r[3]) : "r"(addr));
}
__device__ __forceinline__ unsigned pack_h2(float a, float b) {
    __half2 h = __floats2half2_rn(a, b);
    return *(unsigned*)&h;
}

// window-layout row -> token index (cyclic shift by +3 both axes)
__device__ __forceinline__ size_t win_row_to_token(int r) {
    int win = r / 49;
    int n   = r - win * 49;
    int b   = win >> 6;
    int wi  = win & 63;
    int ri  = n / 7;
    int ci  = n - ri * 7;
    int hs = (wi >> 3) * 7 + ri + 3; if (hs >= 56) hs -= 56;
    int ws = (wi & 7)  * 7 + ci + 3; if (ws >= 56) ws -= 56;
    return (size_t)b * 3136 + (size_t)hs * 56 + ws;
}

// ---------------- all-weights fp32 -> interleaved fp16 (single launch) ----------------
__global__ __launch_bounds__(256)
void w2h_all(const float* __restrict__ qkv_w, const float* __restrict__ proj_w,
             const float* __restrict__ fc1_w, const float* __restrict__ fc2_w,
             __half2* __restrict__ out) {
    int i = blockIdx.x * 256 + threadIdx.x;
    if (i >= W_TOT) return;
    const float* w; int N, base;
    if      (i < W_PROJ) { w = qkv_w;  N = QKV3;   base = W_QKV;  }
    else if (i < W_FC1)  { w = proj_w; N = CDIM;   base = W_PROJ; }
    else if (i < W_FC2)  { w = fc1_w;  N = HIDDEN; base = W_FC1;  }
    else                 { w = fc2_w;  N = CDIM;   base = W_FC2;  }
    int j = i - base;
    int kq = j / N, n = j - kq * N;
    out[i] = __halves2half2(__float2half(w[(size_t)(2 * kq) * N + n]),
                            __float2half(w[(size_t)(2 * kq + 1) * N + n]));
}

// ---------------- bias+mask table precompute ----------------
__global__ __launch_bounds__(256)
void bias_tbl(const float* __restrict__ rpb, float* __restrict__ tbl) {
    int idx = blockIdx.x * 256 + threadIdx.x;
    if (idx >= BTAB_N) return;
    int cls  = idx / (6 * 2401);
    int rem  = idx - cls * 6 * 2401;
    int head = rem / 2401;
    int e    = rem - head * 2401;
    int i = e / 49, j = e - i * 49;
    int yi = i / 7, xi = i - yi * 7;
    int yj = j / 7, xj = j - yj * 7;
    float v = rpb[((yi - yj + 6) * 13 + (xi - xj + 6)) * 6 + head];
    bool wy7 = (cls & 2) != 0, wx7 = (cls & 1) != 0;
    int gri = wy7 ? (yi < 4 ? 1 : 2) : 0;
    int gci = wx7 ? (xi < 4 ? 1 : 2) : 0;
    int grj = wy7 ? (yj < 4 ? 1 : 2) : 0;
    int gcj = wx7 ? (xj < 4 ? 1 : 2) : 0;
    if (gri * 3 + gci != grj * 3 + gcj) v -= 100.f;
    tbl[idx] = v;
}

// ---------------- LayerNorm (1 warp per row), fp16 output ----------------
template<bool GATHER>
__global__ __launch_bounds__(256)
void ln_kernel(const float* __restrict__ in, const float* __restrict__ gamma,
               const float* __restrict__ beta, __half* __restrict__ out) {
    int row  = blockIdx.x * 8 + (threadIdx.x >> 5);
    int lane = threadIdx.x & 31;
    size_t t = GATHER ? win_row_to_token(row) : (size_t)row;
    const float* p = in + t * CDIM;
    float v[6];
    float s = 0.f, ss = 0.f;
#pragma unroll
    for (int i = 0; i < 6; i++) {
        v[i] = p[lane + 32 * i];
        s  += v[i];
        ss += v[i] * v[i];
    }
#pragma unroll
    for (int o = 16; o; o >>= 1) {
        s  += __shfl_xor_sync(0xffffffffu, s, o);
        ss += __shfl_xor_sync(0xffffffffu, ss, o);
    }
    float mu   = s * (1.f / CDIM);
    float var  = ss * (1.f / CDIM) - mu * mu;
    float rinv = rsqrtf(var + 1e-5f);
    __half* q = out + (size_t)row * CDIM;
#pragma unroll
    for (int i = 0; i < 6; i++) {
        int c = lane + 32 * i;
        q[c] = __float2half((v[i] - mu) * rinv * gamma[c] + beta[c]);
    }
}

// ---------------- fp16 mma.sync GEMM, cp.async 3-stage, ldmatrix A, fused epilogues ----
// MODE 0: Ch = A@B + bias                      (qkv, fp16 out)
// MODE 1: d_out[token] = x[token] + A@B + bias (proj + window-reverse + residual, fp32)
// MODE 2: Ch = gelu(A@B + bias)                (fc1, fp16 out)
// MODE 3: Cf += A@B + bias                     (fc2 + residual into d_out, fp32)
template<int MODE>
__global__ __launch_bounds__(128, 4)
void gemm_f16(const __half* __restrict__ A, const __half2* __restrict__ Bw,
              const float* __restrict__ bias, void* __restrict__ Cv,
              const float* __restrict__ extra, int K, int N) {
    extern __shared__ __align__(16) char smem[];

    const int tid  = threadIdx.x;
    const int warp = tid >> 5;
    const int lane = tid & 31;
    const int row0 = blockIdx.y * TM;
    const int col0 = blockIdx.x * TN;
    const int wm = (warp & 1) * 64;
    const int wn = (warp >> 1) * 32;
    const int g  = lane >> 2;
    const int tq = lane & 3;
    const int nk = K >> 5;
    const uint32_t sm_u = smem_u32(smem);
    const uint32_t lm_lane = (uint32_t)(((wm + (lane & 15)) * A_PITCH + ((lane >> 4) * 8)) * 2);

    auto issue = [&](int kb, int s) {
        uint32_t st = sm_u + (uint32_t)s * STAGE_BYTES;
        const __half* Abase = A + (size_t)row0 * K + kb * 32;
#pragma unroll
        for (int u = 0; u < 4; u++) {
            int idx = tid + u * 128;
            int m = idx >> 2, c = idx & 3;
            cpa16(st + (uint32_t)(m * A_PITCH + c * 8) * 2, Abase + (size_t)m * K + c * 8);
        }
        uint32_t bt = st + ASZ_H * 2;
        const __half2* Bbase = Bw + (size_t)(kb * 16) * N + col0;
#pragma unroll
        for (int u = 0; u < 2; u++) {
            int idx = tid + u * 128;
            int kq = idx >> 4, c = idx & 15;
            cpa16(bt + (uint32_t)(kq * B_PITCH + c * 4) * 4, Bbase + (size_t)kq * N + c * 4);
        }
    };

    float acc[4][4][4];
#pragma unroll
    for (int mi = 0; mi < 4; mi++)
#pragma unroll
        for (int ni = 0; ni < 4; ni++)
#pragma unroll
            for (int j = 0; j < 4; j++) acc[mi][ni][j] = 0.f;

    issue(0, 0); CP_COMMIT();
    issue(1, 1); CP_COMMIT();

    for (int kb = 0; kb < nk; kb++) {
        if (kb + 2 < nk) { CP_WAIT1(); } else { CP_WAIT0(); }
        __syncthreads();
        int s = kb % NSTAGE;
        if (kb + 2 < nk) { issue(kb + 2, (kb + 2) % NSTAGE); CP_COMMIT(); }

        uint32_t a_u = sm_u + (uint32_t)s * STAGE_BYTES + lm_lane;
        const __half2* b = (const __half2*)(smem + (size_t)s * STAGE_BYTES + ASZ_H * 2);
#pragma unroll
        for (int ks = 0; ks < 2; ks++) {
            unsigned af[4][4], bf[4][2];
#pragma unroll
            for (int mi = 0; mi < 4; mi++)
                ldsm_x4(af[mi], a_u + (uint32_t)((mi * 16 * A_PITCH + ks * 16) * 2));
#pragma unroll
            for (int ni = 0; ni < 4; ni++) {
                int n0 = wn + ni * 8;
                bf[ni][0] = *(const unsigned*)(b + (ks * 8 + tq)     * B_PITCH + n0 + g);
                bf[ni][1] = *(const unsigned*)(b + (ks * 8 + tq + 4) * B_PITCH + n0 + g);
            }
#pragma unroll
            for (int mi = 0; mi < 4; mi++)
#pragma unroll
                for (int ni = 0; ni < 4; ni++)
                    mma_f16(acc[mi][ni], af[mi], bf[ni]);
        }
        __syncthreads();
    }

    float* Cf = (float*)Cv;
    __half* Ch = (__half*)Cv;
#pragma unroll
    for (int mi = 0; mi < 4; mi++) {
#pragma unroll
        for (int h = 0; h < 2; h++) {
            int r = row0 + wm + mi * 16 + g + h * 8;
            float* dstf = nullptr;
            const float* xrow = nullptr;
            if (MODE == 1) {
                size_t t = win_row_to_token(r);
                dstf = Cf + t * CDIM;
                xrow = extra + t * CDIM;
            } else if (MODE == 3) {
                dstf = Cf + (size_t)r * N;
            }
#pragma unroll
            for (int ni = 0; ni < 4; ni++) {
                int c = col0 + wn + ni * 8 + tq * 2;
                float ox = acc[mi][ni][h * 2 + 0] + bias[c];
                float oy = acc[mi][ni][h * 2 + 1] + bias[c + 1];
                if (MODE == 0) {
                    *(__half2*)(Ch + (size_t)r * N + c) =
                        __halves2half2(__float2half(ox), __float2half(oy));
                } else if (MODE == 1) {
                    float2 xv = *(const float2*)(xrow + c);
                    float2 o = {ox + xv.x, oy + xv.y};
                    *(float2*)(dstf + c) = o;
                } else if (MODE == 2) {
                    ox = 0.5f * ox * (1.f + erff(ox * 0.70710678118654752f));
                    oy = 0.5f * oy * (1.f + erff(oy * 0.70710678118654752f));
                    *(__half2*)(Ch + (size_t)r * N + c) =
                        __halves2half2(__float2half(ox), __float2half(oy));
                } else {
                    float2 cv = *(const float2*)(dstf + c);
                    float2 o = {ox + cv.x, oy + cv.y};
                    *(float2*)(dstf + c) = o;
                }
            }
        }
    }
}

// ---------------- tensor-core windowed attention: 1 block per (window, head) ----------
// Q,K padded 49->64; softmax fully in registers; P reused as mma A-fragments.
// bias+mask from precomputed table (SMEM-resident).
#define QK_PITCH 40     // halves per Q/K row
#define VT_PITCH 72     // halves per Vt row
__global__ __launch_bounds__(128)
void attn_tc(const __half* __restrict__ qkv, const float* __restrict__ btab,
             __half* __restrict__ outp) {
    __shared__ __align__(16) __half sQ[64 * QK_PITCH];    // 320 uint4
    __shared__ __align__(16) __half sK[64 * QK_PITCH];    // 320 uint4
    __shared__ __align__(16) __half sVt[32 * VT_PITCH];   // 288 uint4
    __shared__ float sT[2401];

    const int blk = blockIdx.x;
    const int win = blk / 6, head = blk % 6;
    const int tid = threadIdx.x, warp = tid >> 5, lane = tid & 31;
    const int g = lane >> 2, tq = lane & 3;

    // zero all tiles (padding rows/cols must be 0)
    {
        uint4 z4 = {0, 0, 0, 0};
        uint4* zq = (uint4*)sQ;
        uint4* zk = (uint4*)sK;
        uint4* zv = (uint4*)sVt;
#pragma unroll
        for (int u = 0; u < 2; u++) { zq[tid + u * 128] = z4; zk[tid + u * 128] = z4; zv[tid + u * 128] = z4; }
        if (tid < 64) { zq[tid + 256] = z4; zk[tid + 256] = z4; }
        if (tid < 32) zv[tid + 256] = z4;
    }
    // bias+mask table slice
    const int wi = win & 63;
    const int wy = wi >> 3, wx = wi & 7;
    const int cls = ((wy == 7) ? 2 : 0) | ((wx == 7) ? 1 : 0);
    const float* tb = btab + (size_t)(cls * 6 + head) * 2401;
    for (int t = tid; t < 2401; t += 128) sT[t] = tb[t];

    const __half* base = qkv + (size_t)win * 49 * QKV3 + head * 32;
    // Q, K: 49 rows x 4 chunks of 8 halves
    for (int t = tid; t < 49 * 4; t += 128) {
        int n = t >> 2, c = t & 3;
        *(uint4*)(sQ + n * QK_PITCH + c * 8) = *(const uint4*)(base + (size_t)n * QKV3 + c * 8);
        *(uint4*)(sK + n * QK_PITCH + c * 8) = *(const uint4*)(base + (size_t)n * QKV3 + 192 + c * 8);
    }
    // V transpose: V[j][d] -> Vt[d][j]
    for (int t = tid; t < 49 * 16; t += 128) {
        int j = t >> 4, dp = t & 15;
        __half2 h = *(const __half2*)(base + (size_t)j * QKV3 + 384 + dp * 2);
        sVt[(dp * 2)     * VT_PITCH + j] = __low2half(h);
        sVt[(dp * 2 + 1) * VT_PITCH + j] = __high2half(h);
    }
    __syncthreads();

    // ---- QK^T: per warp rows wm..wm+15 ----
    const int wm = warp * 16;
    unsigned aq[2][4];
    {
        uint32_t a_u = smem_u32(sQ) + (uint32_t)(((wm + (lane & 15)) * QK_PITCH + (lane >> 4) * 8) * 2);
        ldsm_x4(aq[0], a_u);
        ldsm_x4(aq[1], a_u + 32);
    }
    float sc[8][4];
#pragma unroll
    for (int nt = 0; nt < 8; nt++) {
        sc[nt][0] = sc[nt][1] = sc[nt][2] = sc[nt][3] = 0.f;
        const __half* kr = sK + (nt * 8 + g) * QK_PITCH + tq * 2;
        unsigned bfa[2] = { *(const unsigned*)kr,        *(const unsigned*)(kr + 8)  };
        unsigned bfb[2] = { *(const unsigned*)(kr + 16), *(const unsigned*)(kr + 24) };
        mma_f16(sc[nt], aq[0], bfa);
        mma_f16(sc[nt], aq[1], bfb);
    }

    // ---- softmax in registers (table supplies bias+mask) ----
    int ib[2];
    bool rowok[2];
#pragma unroll
    for (int r = 0; r < 2; r++) {
        int i = wm + g + r * 8;
        rowok[r] = (i < 49);
        ib[r] = (rowok[r] ? i : 0) * 49;
    }
    float vmax[2] = {-1e30f, -1e30f};
#pragma unroll
    for (int nt = 0; nt < 8; nt++) {
#pragma unroll
        for (int c = 0; c < 4; c++) {
            int j = nt * 8 + tq * 2 + (c & 1);
            int r = c >> 1;
            float v;
            if (j < 49 && rowok[r]) {
                v = fmaf(sc[nt][c], 0.17677669529663687f, sT[ib[r] + j]);
            } else {
                v = -1e30f;
            }
            sc[nt][c] = v;
            vmax[r] = fmaxf(vmax[r], v);
        }
    }
#pragma unroll
    for (int r = 0; r < 2; r++) {
        vmax[r] = fmaxf(vmax[r], __shfl_xor_sync(0xffffffffu, vmax[r], 1));
        vmax[r] = fmaxf(vmax[r], __shfl_xor_sync(0xffffffffu, vmax[r], 2));
    }
    float vsum[2] = {0.f, 0.f};
#pragma unroll
    for (int nt = 0; nt < 8; nt++) {
#pragma unroll
        for (int c = 0; c < 4; c++) {
            int r = c >> 1;
            float e = __expf(sc[nt][c] - vmax[r]);
            sc[nt][c] = e;
            vsum[r] += e;
        }
    }
#pragma unroll
    for (int r = 0; r < 2; r++) {
        vsum[r] += __shfl_xor_sync(0xffffffffu, vsum[r], 1);
        vsum[r] += __shfl_xor_sync(0xffffffffu, vsum[r], 2);
    }
    float inv0 = 1.f / vsum[0], inv1 = 1.f / vsum[1];

    // ---- P as A-fragments, PV ----
    unsigned ap[4][4];
#pragma unroll
    for (int kc = 0; kc < 4; kc++) {
        ap[kc][0] = pack_h2(sc[2 * kc][0],     sc[2 * kc][1]);
        ap[kc][1] = pack_h2(sc[2 * kc][2],     sc[2 * kc][3]);
        ap[kc][2] = pack_h2(sc[2 * kc + 1][0], sc[2 * kc + 1][1]);
        ap[kc][3] = pack_h2(sc[2 * kc + 1][2], sc[2 * kc + 1][3]);
    }
    float oacc[4][4];
#pragma unroll
    for (int dt = 0; dt < 4; dt++) {
        oacc[dt][0] = oacc[dt][1] = oacc[dt][2] = oacc[dt][3] = 0.f;
#pragma unroll
        for (int kc = 0; kc < 4; kc++) {
            const __half* vr = sVt + (dt * 8 + g) * VT_PITCH + kc * 16 + tq * 2;
            unsigned bf[2] = { *(const unsigned*)vr, *(const unsigned*)(vr + 8) };
            mma_f16(oacc[dt], ap[kc], bf);
        }
    }

    // ---- store ----
#pragma unroll
    for (int r = 0; r < 2; r++) {
        int i = wm + g + r * 8;
        if (i < 49) {
            float invr = r ? inv1 : inv0;
            __half* dst = outp + ((size_t)win * 49 + i) * CDIM + head * 32;
#pragma unroll
            for (int dt = 0; dt < 4; dt++) {
                float ox = oacc[dt][r * 2 + 0] * invr;
                float oy = oacc[dt][r * 2 + 1] * invr;
                *(__half2*)(dst + dt * 8 + tq * 2) = __floats2half2_rn(ox, oy);
            }
        }
    }
}

// ---------------- launch ----------------
extern "C" void kernel_launch(void* const* d_in, const int* in_sizes, int n_in,
                              void* d_out, int out_size) {
    const float* x      = (const float*)d_in[0];
    const float* n1g    = (const float*)d_in[1];
    const float* n1b    = (const float*)d_in[2];
    const float* qkv_w  = (const float*)d_in[3];
    const float* qkv_b  = (const float*)d_in[4];
    const float* rpb    = (const float*)d_in[5];
    const float* proj_w = (const float*)d_in[6];
    const float* proj_b = (const float*)d_in[7];
    const float* n2g    = (const float*)d_in[8];
    const float* n2b    = (const float*)d_in[9];
    const float* fc1_w  = (const float*)d_in[10];
    const float* fc1_b  = (const float*)d_in[11];
    const float* fc2_w  = (const float*)d_in[12];
    const float* fc2_b  = (const float*)d_in[13];
    float* out = (float*)d_out;

    __half *p_xw, *p_qkv, *p_attn, *p_y, *p_h;
    __half2 *p_w16;
    float *p_btab;
    cudaGetSymbolAddress((void**)&p_xw,   g_xw);
    cudaGetSymbolAddress((void**)&p_qkv,  g_qkv);
    cudaGetSymbolAddress((void**)&p_attn, g_attn);
    cudaGetSymbolAddress((void**)&p_y,    g_y);
    cudaGetSymbolAddress((void**)&p_h,    g_h);
    cudaGetSymbolAddress((void**)&p_w16,  g_w16);
    cudaGetSymbolAddress((void**)&p_btab, g_btab);

    cudaFuncSetAttribute(gemm_f16<0>, cudaFuncAttributeMaxDynamicSharedMemorySize, SMEM_SZ);
    cudaFuncSetAttribute(gemm_f16<1>, cudaFuncAttributeMaxDynamicSharedMemorySize, SMEM_SZ);
    cudaFuncSetAttribute(gemm_f16<2>, cudaFuncAttributeMaxDynamicSharedMemorySize, SMEM_SZ);
    cudaFuncSetAttribute(gemm_f16<3>, cudaFuncAttributeMaxDynamicSharedMemorySize, SMEM_SZ);

    const int MT = M_ROWS / TM;   // 784

    // 0. weight conversion + bias table
    w2h_all<<<(W_TOT + 255) / 256, 256>>>(qkv_w, proj_w, fc1_w, fc2_w, p_w16);
    bias_tbl<<<(BTAB_N + 255) / 256, 256>>>(rpb, p_btab);

    // 1. LN1 + shift + window partition (fp16 out)
    ln_kernel<true><<<M_ROWS / 8, 256>>>(x, n1g, n1b, p_xw);
    // 2. QKV projection (fp16 out)
    gemm_f16<0><<<dim3(QKV3 / TN, MT), 128, SMEM_SZ>>>(p_xw, p_w16 + W_QKV, qkv_b, p_qkv, nullptr, CDIM, QKV3);
    // 3. tensor-core windowed attention (fp16 in/out)
    attn_tc<<<2048 * 6, 128>>>(p_qkv, p_btab, p_attn);
    // 4. proj + window reverse + un-shift + residual -> d_out holds x1 (fp32)
    gemm_f16<1><<<dim3(CDIM / TN, MT), 128, SMEM_SZ>>>(p_attn, p_w16 + W_PROJ, proj_b, out, x, CDIM, CDIM);
    // 5. LN2 (fp16 out)
    ln_kernel<false><<<M_ROWS / 8, 256>>>(out, n2g, n2b, p_y);
    // 6. FC1 + GELU (fp16 out)
    gemm_f16<2><<<dim3(HIDDEN / TN, MT), 128, SMEM_SZ>>>(p_y, p_w16 + W_FC1, fc1_b, p_h, nullptr, CDIM, HIDDEN);
    // 7. FC2 + residual add into d_out (fp32)
    gemm_f16<3><<<dim3(CDIM / TN, MT), 128, SMEM_SZ>>>(p_h, p_w16 + W_FC2, fc2_b, out, nullptr, HIDDEN, CDIM);
}

// round 16
// speedup vs baseline: 1.1079x; 1.0059x over previous
#include <cuda_runtime.h>
#include <cuda_fp16.h>
#include <math.h>
#include <stdint.h>

#define M_ROWS 100352   // 32 * 3136 = 2048 windows * 49
#define CDIM   192
#define HIDDEN 768
#define QKV3   576

// GEMM tiling: block 128x64, 8 warps of 32x32 (4M x 2N), 3-stage cp.async, fp16
#define TM 128
#define TN 64
#define NSTAGE 3
#define A_PITCH 40                    // halves per A row: 80B pitch -> ldmatrix conflict-free
#define B_PITCH 72                    // half2 per B k-pair row: bank = (8tq+g)%32, distinct
#define ASZ_H  (TM * A_PITCH)         // 5120 halves / stage
#define BSZ_H2 (16 * B_PITCH)         // 1152 half2 / stage
#define STAGE_BYTES (ASZ_H * 2 + BSZ_H2 * 4)   // 14848
#define SMEM_SZ (NSTAGE * STAGE_BYTES)         // 44544

// ---------------- scratch (no allocs allowed) ----------------
__device__ __align__(16) __half  g_xw  [(size_t)M_ROWS * CDIM];
__device__ __align__(16) __half  g_qkv [(size_t)M_ROWS * QKV3];
__device__ __align__(16) __half  g_attn[(size_t)M_ROWS * CDIM];
__device__ __align__(16) __half  g_y   [(size_t)M_ROWS * CDIM];
__device__ __align__(16) __half  g_h   [(size_t)M_ROWS * HIDDEN];
// fp16 weights, k-pair interleaved half2: w16[(k/2)*N + n] = (w[k][n], w[k+1][n])
#define W_QKV  0
#define W_PROJ 55296
#define W_FC1  73728
#define W_FC2  147456
#define W_TOT  221184
__device__ __align__(16) __half2 g_w16[W_TOT];

// ---------------- helpers ----------------
__device__ __forceinline__ uint32_t smem_u32(const void* p) {
    uint32_t a;
    asm("{ .reg .u64 t; cvta.to.shared.u64 t, %1; cvt.u32.u64 %0, t; }" : "=r"(a) : "l"(p));
    return a;
}
__device__ __forceinline__ void cpa16(uint32_t dst, const void* src) {
    asm volatile("cp.async.cg.shared.global [%0], [%1], 16;" :: "r"(dst), "l"(src));
}
#define CP_COMMIT() asm volatile("cp.async.commit_group;" ::: "memory")
#define CP_WAIT1()  asm volatile("cp.async.wait_group 1;" ::: "memory")
#define CP_WAIT0()  asm volatile("cp.async.wait_group 0;" ::: "memory")

__device__ __forceinline__ void mma_f16(float c[4], const unsigned a[4], const unsigned b[2]) {
    asm volatile(
        "mma.sync.aligned.m16n8k16.row.col.f32.f16.f16.f32 "
        "{%0,%1,%2,%3}, {%4,%5,%6,%7}, {%8,%9}, {%0,%1,%2,%3};"
        : "+f"(c[0]), "+f"(c[1]), "+f"(c[2]), "+f"(c[3])
        : "r"(a[0]), "r"(a[1]), "r"(a[2]), "r"(a[3]), "r"(b[0]), "r"(b[1]));
}
__device__ __forceinline__ void ldsm_x4(unsigned r[4], uint32_t addr) {
    asm volatile("ldmatrix.sync.aligned.m8n8.x4.shared.b16 {%0,%1,%2,%3}, [%4];"
        : "=r"(r[0]), "=r"(r[1]), "=r"(r[2]), "=r"(r[3]) : "r"(addr));
}
__device__ __forceinline__ unsigned pack_h2(float a, float b) {
    __half2 h = __floats2half2_rn(a, b);
    return *(unsigned*)&h;
}

// window-layout row -> token index (cyclic shift by +3 both axes)
__device__ __forceinline__ size_t win_row_to_token(int r) {
    int win = r / 49;
    int n   = r - win * 49;
    int b   = win >> 6;
    int wi  = win & 63;
    int ri  = n / 7;
    int ci  = n - ri * 7;
    int hs = (wi >> 3) * 7 + ri + 3; if (hs >= 56) hs -= 56;
    int ws = (wi & 7)  * 7 + ci + 3; if (ws >= 56) ws -= 56;
    return (size_t)b * 3136 + (size_t)hs * 56 + ws;
}

// ---------------- all-weights fp32 -> interleaved fp16 (single launch) ----------------
__global__ __launch_bounds__(256)
void w2h_all(const float* __restrict__ qkv_w, const float* __restrict__ proj_w,
             const float* __restrict__ fc1_w, const float* __restrict__ fc2_w,
             __half2* __restrict__ out) {
    int i = blockIdx.x * 256 + threadIdx.x;
    if (i >= W_TOT) return;
    const float* w; int N, base;
    if      (i < W_PROJ) { w = qkv_w;  N = QKV3;   base = W_QKV;  }
    else if (i < W_FC1)  { w = proj_w; N = CDIM;   base = W_PROJ; }
    else if (i < W_FC2)  { w = fc1_w;  N = HIDDEN; base = W_FC1;  }
    else                 { w = fc2_w;  N = CDIM;   base = W_FC2;  }
    int j = i - base;
    int kq = j / N, n = j - kq * N;
    out[i] = __halves2half2(__float2half(w[(size_t)(2 * kq) * N + n]),
                            __float2half(w[(size_t)(2 * kq + 1) * N + n]));
}

// ---------------- LayerNorm (1 warp per row), fp16 output ----------------
template<bool GATHER>
__global__ __launch_bounds__(256)
void ln_kernel(const float* __restrict__ in, const float* __restrict__ gamma,
               const float* __restrict__ beta, __half* __restrict__ out) {
    int row  = blockIdx.x * 8 + (threadIdx.x >> 5);
    int lane = threadIdx.x & 31;
    size_t t = GATHER ? win_row_to_token(row) : (size_t)row;
    const float* p = in + t * CDIM;
    float v[6];
    float s = 0.f, ss = 0.f;
#pragma unroll
    for (int i = 0; i < 6; i++) {
        v[i] = p[lane + 32 * i];
        s  += v[i];
        ss += v[i] * v[i];
    }
#pragma unroll
    for (int o = 16; o; o >>= 1) {
        s  += __shfl_xor_sync(0xffffffffu, s, o);
        ss += __shfl_xor_sync(0xffffffffu, ss, o);
    }
    float mu   = s * (1.f / CDIM);
    float var  = ss * (1.f / CDIM) - mu * mu;
    float rinv = rsqrtf(var + 1e-5f);
    __half* q = out + (size_t)row * CDIM;
#pragma unroll
    for (int i = 0; i < 6; i++) {
        int c = lane + 32 * i;
        q[c] = __float2half((v[i] - mu) * rinv * gamma[c] + beta[c]);
    }
}

// ---------------- fp16 mma.sync GEMM: 256 thr, 8 warps of 32x32, 3-stage ----------------
// MODE 0: Ch = A@B + bias                      (qkv, fp16 out)
// MODE 1: d_out[token] = x[token] + A@B + bias (proj + window-reverse + residual, fp32)
// MODE 2: Ch = gelu(A@B + bias)                (fc1, fp16 out)
// MODE 3: Cf += A@B + bias                     (fc2 + residual into d_out, fp32)
template<int MODE>
__global__ __launch_bounds__(256, 3)
void gemm_f16(const __half* __restrict__ A, const __half2* __restrict__ Bw,
              const float* __restrict__ bias, void* __restrict__ Cv,
              const float* __restrict__ extra, int K, int N) {
    extern __shared__ __align__(16) char smem[];

    const int tid  = threadIdx.x;
    const int warp = tid >> 5;
    const int lane = tid & 31;
    const int row0 = blockIdx.y * TM;
    const int col0 = blockIdx.x * TN;
    const int wm = (warp & 3) * 32;        // 4 warps along M
    const int wn = (warp >> 2) * 32;       // 2 warps along N
    const int g  = lane >> 2;
    const int tq = lane & 3;
    const int nk = K >> 5;
    const uint32_t sm_u = smem_u32(smem);
    const uint32_t lm_lane = (uint32_t)(((wm + (lane & 15)) * A_PITCH + ((lane >> 4) * 8)) * 2);

    auto issue = [&](int kb, int s) {
        uint32_t st = sm_u + (uint32_t)s * STAGE_BYTES;
        const __half* Abase = A + (size_t)row0 * K + kb * 32;
#pragma unroll
        for (int u = 0; u < 2; u++) {
            int idx = tid + u * 256;            // 0..511: m = idx/4, chunk c = idx%4 (8 halves)
            int m = idx >> 2, c = idx & 3;
            cpa16(st + (uint32_t)(m * A_PITCH + c * 8) * 2, Abase + (size_t)m * K + c * 8);
        }
        uint32_t bt = st + ASZ_H * 2;
        const __half2* Bbase = Bw + (size_t)(kb * 16) * N + col0;
        {
            int kq = tid >> 4, c = tid & 15;    // 256 chunks exactly
            cpa16(bt + (uint32_t)(kq * B_PITCH + c * 4) * 4, Bbase + (size_t)kq * N + c * 4);
        }
    };

    float acc[2][4][4];
#pragma unroll
    for (int mi = 0; mi < 2; mi++)
#pragma unroll
        for (int ni = 0; ni < 4; ni++)
#pragma unroll
            for (int j = 0; j < 4; j++) acc[mi][ni][j] = 0.f;

    issue(0, 0); CP_COMMIT();
    issue(1, 1); CP_COMMIT();

    for (int kb = 0; kb < nk; kb++) {
        if (kb + 2 < nk) { CP_WAIT1(); } else { CP_WAIT0(); }
        __syncthreads();                 // single barrier per iteration (see analysis)
        int s = kb % NSTAGE;
        if (kb + 2 < nk) { issue(kb + 2, (kb + 2) % NSTAGE); CP_COMMIT(); }

        uint32_t a_u = sm_u + (uint32_t)s * STAGE_BYTES + lm_lane;
        const __half2* b = (const __half2*)(smem + (size_t)s * STAGE_BYTES + ASZ_H * 2);
#pragma unroll
        for (int ks = 0; ks < 2; ks++) {
            unsigned af[2][4], bf[4][2];
#pragma unroll
            for (int mi = 0; mi < 2; mi++)
                ldsm_x4(af[mi], a_u + (uint32_t)((mi * 16 * A_PITCH + ks * 16) * 2));
#pragma unroll
            for (int ni = 0; ni < 4; ni++) {
                int n0 = wn + ni * 8;
                bf[ni][0] = *(const unsigned*)(b + (ks * 8 + tq)     * B_PITCH + n0 + g);
                bf[ni][1] = *(const unsigned*)(b + (ks * 8 + tq + 4) * B_PITCH + n0 + g);
            }
#pragma unroll
            for (int mi = 0; mi < 2; mi++)
#pragma unroll
                for (int ni = 0; ni < 4; ni++)
                    mma_f16(acc[mi][ni], af[mi], bf[ni]);
        }
    }

    float* Cf = (float*)Cv;
    __half* Ch = (__half*)Cv;
#pragma unroll
    for (int mi = 0; mi < 2; mi++) {
#pragma unroll
        for (int h = 0; h < 2; h++) {
            int r = row0 + wm + mi * 16 + g + h * 8;
            float* dstf = nullptr;
            const float* xrow = nullptr;
            if (MODE == 1) {
                size_t t = win_row_to_token(r);
                dstf = Cf + t * CDIM;
                xrow = extra + t * CDIM;
            } else if (MODE == 3) {
                dstf = Cf + (size_t)r * N;
            }
#pragma unroll
            for (int ni = 0; ni < 4; ni++) {
                int c = col0 + wn + ni * 8 + tq * 2;
                float ox = acc[mi][ni][h * 2 + 0] + bias[c];
                float oy = acc[mi][ni][h * 2 + 1] + bias[c + 1];
                if (MODE == 0) {
                    *(__half2*)(Ch + (size_t)r * N + c) =
                        __halves2half2(__float2half(ox), __float2half(oy));
                } else if (MODE == 1) {
                    float2 xv = *(const float2*)(xrow + c);
                    float2 o = {ox + xv.x, oy + xv.y};
                    *(float2*)(dstf + c) = o;
                } else if (MODE == 2) {
                    ox = 0.5f * ox * (1.f + erff(ox * 0.70710678118654752f));
                    oy = 0.5f * oy * (1.f + erff(oy * 0.70710678118654752f));
                    *(__half2*)(Ch + (size_t)r * N + c) =
                        __halves2half2(__float2half(ox), __float2half(oy));
                } else {
                    float2 cv = *(const float2*)(dstf + c);
                    float2 o = {ox + cv.x, oy + cv.y};
                    *(float2*)(dstf + c) = o;
                }
            }
        }
    }
}

// ---------------- tensor-core windowed attention (R13 winner): 1 block / (window,head) --
#define QK_PITCH 40     // halves per Q/K row
#define VT_PITCH 72     // halves per Vt row
__global__ __launch_bounds__(128)
void attn_tc(const __half* __restrict__ qkv, const float* __restrict__ rpb,
             __half* __restrict__ outp) {
    __shared__ __align__(16) __half sQ[64 * QK_PITCH];    // 320 uint4
    __shared__ __align__(16) __half sK[64 * QK_PITCH];    // 320 uint4
    __shared__ __align__(16) __half sVt[32 * VT_PITCH];   // 288 uint4
    __shared__ float sB[169];

    const int blk = blockIdx.x;
    const int win = blk / 6, head = blk % 6;
    const int tid = threadIdx.x, warp = tid >> 5, lane = tid & 31;
    const int g = lane >> 2, tq = lane & 3;

    {
        uint4 z4 = {0, 0, 0, 0};
        uint4* zq = (uint4*)sQ;
        uint4* zk = (uint4*)sK;
        uint4* zv = (uint4*)sVt;
#pragma unroll
        for (int u = 0; u < 2; u++) { zq[tid + u * 128] = z4; zk[tid + u * 128] = z4; zv[tid + u * 128] = z4; }
        if (tid < 64) { zq[tid + 256] = z4; zk[tid + 256] = z4; }
        if (tid < 32) zv[tid + 256] = z4;
    }
    for (int t = tid; t < 169; t += 128) sB[t] = rpb[t * 6 + head];
    __syncthreads();

    const __half* base = qkv + (size_t)win * 49 * QKV3 + head * 32;
    for (int t = tid; t < 49 * 4; t += 128) {
        int n = t >> 2, c = t & 3;
        *(uint4*)(sQ + n * QK_PITCH + c * 8) = *(const uint4*)(base + (size_t)n * QKV3 + c * 8);
        *(uint4*)(sK + n * QK_PITCH + c * 8) = *(const uint4*)(base + (size_t)n * QKV3 + 192 + c * 8);
    }
    for (int t = tid; t < 49 * 16; t += 128) {
        int j = t >> 4, dp = t & 15;
        __half2 h = *(const __half2*)(base + (size_t)j * QKV3 + 384 + dp * 2);
        sVt[(dp * 2)     * VT_PITCH + j] = __low2half(h);
        sVt[(dp * 2 + 1) * VT_PITCH + j] = __high2half(h);
    }
    __syncthreads();

    const int wm = warp * 16;
    unsigned aq[2][4];
    {
        uint32_t a_u = smem_u32(sQ) + (uint32_t)(((wm + (lane & 15)) * QK_PITCH + (lane >> 4) * 8) * 2);
        ldsm_x4(aq[0], a_u);
        ldsm_x4(aq[1], a_u + 32);
    }
    float sc[8][4];
#pragma unroll
    for (int nt = 0; nt < 8; nt++) {
        sc[nt][0] = sc[nt][1] = sc[nt][2] = sc[nt][3] = 0.f;
        const __half* kr = sK + (nt * 8 + g) * QK_PITCH + tq * 2;
        unsigned bfa[2] = { *(const unsigned*)kr,        *(const unsigned*)(kr + 8)  };
        unsigned bfb[2] = { *(const unsigned*)(kr + 16), *(const unsigned*)(kr + 24) };
        mma_f16(sc[nt], aq[0], bfa);
        mma_f16(sc[nt], aq[1], bfb);
    }

    const int wi = win & 63;
    const int wy = wi >> 3, wx = wi & 7;
    int yi[2], xi[2], gi[2];
    bool rowok[2];
#pragma unroll
    for (int r = 0; r < 2; r++) {
        int i = wm + g + r * 8;
        rowok[r] = (i < 49);
        int ic = rowok[r] ? i : 0;
        yi[r] = ic / 7; xi[r] = ic - yi[r] * 7;
        int ri = wy * 7 + yi[r], ci = wx * 7 + xi[r];
        gi[r] = (ri < 49 ? 0 : (ri < 53 ? 1 : 2)) * 3 + (ci < 49 ? 0 : (ci < 53 ? 1 : 2));
    }
    float vmax[2] = {-1e30f, -1e30f};
#pragma unroll
    for (int nt = 0; nt < 8; nt++) {
#pragma unroll
        for (int c = 0; c < 4; c++) {
            int j = nt * 8 + tq * 2 + (c & 1);
            int r = c >> 1;
            float v = sc[nt][c] * 0.17677669529663687f;
            if (j < 49 && rowok[r]) {
                int yj = j / 7, xj = j - yj * 7;
                v += sB[(yi[r] - yj + 6) * 13 + (xi[r] - xj + 6)];
                int rj = wy * 7 + yj, cj = wx * 7 + xj;
                int gj = (rj < 49 ? 0 : (rj < 53 ? 1 : 2)) * 3 + (cj < 49 ? 0 : (cj < 53 ? 1 : 2));
                if (gi[r] != gj) v -= 100.f;
            } else {
                v = -1e30f;
            }
            sc[nt][c] = v;
            vmax[r] = fmaxf(vmax[r], v);
        }
    }
#pragma unroll
    for (int r = 0; r < 2; r++) {
        vmax[r] = fmaxf(vmax[r], __shfl_xor_sync(0xffffffffu, vmax[r], 1));
        vmax[r] = fmaxf(vmax[r], __shfl_xor_sync(0xffffffffu, vmax[r], 2));
    }
    float vsum[2] = {0.f, 0.f};
#pragma unroll
    for (int nt = 0; nt < 8; nt++) {
#pragma unroll
        for (int c = 0; c < 4; c++) {
            int r = c >> 1;
            float e = __expf(sc[nt][c] - vmax[r]);
            sc[nt][c] = e;
            vsum[r] += e;
        }
    }
#pragma unroll
    for (int r = 0; r < 2; r++) {
        vsum[r] += __shfl_xor_sync(0xffffffffu, vsum[r], 1);
        vsum[r] += __shfl_xor_sync(0xffffffffu, vsum[r], 2);
    }
    float inv0 = 1.f / vsum[0], inv1 = 1.f / vsum[1];

    unsigned ap[4][4];
#pragma unroll
    for (int kc = 0; kc < 4; kc++) {
        ap[kc][0] = pack_h2(sc[2 * kc][0],     sc[2 * kc][1]);
        ap[kc][1] = pack_h2(sc[2 * kc][2],     sc[2 * kc][3]);
        ap[kc][2] = pack_h2(sc[2 * kc + 1][0], sc[2 * kc + 1][1]);
        ap[kc][3] = pack_h2(sc[2 * kc + 1][2], sc[2 * kc + 1][3]);
    }
    float oacc[4][4];
#pragma unroll
    for (int dt = 0; dt < 4; dt++) {
        oacc[dt][0] = oacc[dt][1] = oacc[dt][2] = oacc[dt][3] = 0.f;
#pragma unroll
        for (int kc = 0; kc < 4; kc++) {
            const __half* vr = sVt + (dt * 8 + g) * VT_PITCH + kc * 16 + tq * 2;
            unsigned bf[2] = { *(const unsigned*)vr, *(const unsigned*)(vr + 8) };
            mma_f16(oacc[dt], ap[kc], bf);
        }
    }

#pragma unroll
    for (int r = 0; r < 2; r++) {
        int i = wm + g + r * 8;
        if (i < 49) {
            float invr = r ? inv1 : inv0;
            __half* dst = outp + ((size_t)win * 49 + i) * CDIM + head * 32;
#pragma unroll
            for (int dt = 0; dt < 4; dt++) {
                float ox = oacc[dt][r * 2 + 0] * invr;
                float oy = oacc[dt][r * 2 + 1] * invr;
                *(__half2*)(dst + dt * 8 + tq * 2) = __floats2half2_rn(ox, oy);
            }
        }
    }
}

// ---------------- launch ----------------
extern "C" void kernel_launch(void* const* d_in, const int* in_sizes, int n_in,
                              void* d_out, int out_size) {
    const float* x      = (const float*)d_in[0];
    const float* n1g    = (const float*)d_in[1];
    const float* n1b    = (const float*)d_in[2];
    const float* qkv_w  = (const float*)d_in[3];
    const float* qkv_b  = (const float*)d_in[4];
    const float* rpb    = (const float*)d_in[5];
    const float* proj_w = (const float*)d_in[6];
    const float* proj_b = (const float*)d_in[7];
    const float* n2g    = (const float*)d_in[8];
    const float* n2b    = (const float*)d_in[9];
    const float* fc1_w  = (const float*)d_in[10];
    const float* fc1_b  = (const float*)d_in[11];
    const float* fc2_w  = (const float*)d_in[12];
    const float* fc2_b  = (const float*)d_in[13];
    float* out = (float*)d_out;

    __half *p_xw, *p_qkv, *p_attn, *p_y, *p_h;
    __half2 *p_w16;
    cudaGetSymbolAddress((void**)&p_xw,   g_xw);
    cudaGetSymbolAddress((void**)&p_qkv,  g_qkv);
    cudaGetSymbolAddress((void**)&p_attn, g_attn);
    cudaGetSymbolAddress((void**)&p_y,    g_y);
    cudaGetSymbolAddress((void**)&p_h,    g_h);
    cudaGetSymbolAddress((void**)&p_w16,  g_w16);

    cudaFuncSetAttribute(gemm_f16<0>, cudaFuncAttributeMaxDynamicSharedMemorySize, SMEM_SZ);
    cudaFuncSetAttribute(gemm_f16<1>, cudaFuncAttributeMaxDynamicSharedMemorySize, SMEM_SZ);
    cudaFuncSetAttribute(gemm_f16<2>, cudaFuncAttributeMaxDynamicSharedMemorySize, SMEM_SZ);
    cudaFuncSetAttribute(gemm_f16<3>, cudaFuncAttributeMaxDynamicSharedMemorySize, SMEM_SZ);

    const int MT = M_ROWS / TM;   // 784

    // 0. weight conversion (fp32 -> interleaved fp16), single launch
    w2h_all<<<(W_TOT + 255) / 256, 256>>>(qkv_w, proj_w, fc1_w, fc2_w, p_w16);

    // 1. LN1 + shift + window partition (fp16 out)
    ln_kernel<true><<<M_ROWS / 8, 256>>>(x, n1g, n1b, p_xw);
    // 2. QKV projection (fp16 out)
    gemm_f16<0><<<dim3(QKV3 / TN, MT), 256, SMEM_SZ>>>(p_xw, p_w16 + W_QKV, qkv_b, p_qkv, nullptr, CDIM, QKV3);
    // 3. tensor-core windowed attention (fp16 in/out)
    attn_tc<<<2048 * 6, 128>>>(p_qkv, rpb, p_attn);
    // 4. proj + window reverse + un-shift + residual -> d_out holds x1 (fp32)
    gemm_f16<1><<<dim3(CDIM / TN, MT), 256, SMEM_SZ>>>(p_attn, p_w16 + W_PROJ, proj_b, out, x, CDIM, CDIM);
    // 5. LN2 (fp16 out)
    ln_kernel<false><<<M_ROWS / 8, 256>>>(out, n2g, n2b, p_y);
    // 6. FC1 + GELU (fp16 out)
    gemm_f16<2><<<dim3(HIDDEN / TN, MT), 256, SMEM_SZ>>>(p_y, p_w16 + W_FC1, fc1_b, p_h, nullptr, CDIM, HIDDEN);
    // 7. FC2 + residual add into d_out (fp32)
    gemm_f16<3><<<dim3(CDIM / TN, MT), 256, SMEM_SZ>>>(p_h, p_w16 + W_FC2, fc2_b, out, nullptr, HIDDEN, CDIM);
}

// round 17
// speedup vs baseline: 1.1978x; 1.0812x over previous
#include <cuda_runtime.h>
#include <cuda_fp16.h>
#include <math.h>
#include <stdint.h>

#define M_ROWS 100352   // 32 * 3136 = 2048 windows * 49
#define CDIM   192
#define HIDDEN 768
#define QKV3   576

// GEMM tiling: block 128x64, 4 warps of 64x32, 3-stage cp.async, fp16 operands
#define TM 128
#define TN 64
#define NSTAGE 3
#define A_PITCH 40                    // halves per A row: 80B pitch -> ldmatrix conflict-free
#define B_PITCH 72                    // half2 per B k-pair row: bank = (8tq+g)%32, distinct
#define ASZ_H  (TM * A_PITCH)         // 5120 halves / stage
#define BSZ_H2 (16 * B_PITCH)         // 1152 half2 / stage
#define STAGE_BYTES (ASZ_H * 2 + BSZ_H2 * 4)   // 14848
#define SMEM_SZ (NSTAGE * STAGE_BYTES)         // 44544

// ---------------- scratch (no allocs allowed) ----------------
__device__ __align__(16) __half  g_xw  [(size_t)M_ROWS * CDIM];
__device__ __align__(16) __half  g_qkv [(size_t)M_ROWS * QKV3];
__device__ __align__(16) __half  g_attn[(size_t)M_ROWS * CDIM];
__device__ __align__(16) __half  g_y   [(size_t)M_ROWS * CDIM];
__device__ __align__(16) __half  g_h   [(size_t)M_ROWS * HIDDEN];
// fp16 weights, k-pair interleaved half2: w16[(k/2)*N + n] = (w[k][n], w[k+1][n])
#define W_QKV  0
#define W_PROJ 55296
#define W_FC1  73728
#define W_FC2  147456
#define W_TOT  221184
__device__ __align__(16) __half2 g_w16[W_TOT];
// bias+mask table: [cls][head][i][j], rows padded to 50 (float2-aligned), cls=(wy==7)*2|(wx==7)
#define BROW 50
#define BTAB_N (4 * 6 * 49 * BROW)
__device__ __align__(8) float g_btab[BTAB_N];

// ---------------- helpers ----------------
__device__ __forceinline__ uint32_t smem_u32(const void* p) {
    uint32_t a;
    asm("{ .reg .u64 t; cvta.to.shared.u64 t, %1; cvt.u32.u64 %0, t; }" : "=r"(a) : "l"(p));
    return a;
}
__device__ __forceinline__ void cpa16(uint32_t dst, const void* src) {
    asm volatile("cp.async.cg.shared.global [%0], [%1], 16;" :: "r"(dst), "l"(src));
}
#define CP_COMMIT() asm volatile("cp.async.commit_group;" ::: "memory")
#define CP_WAIT1()  asm volatile("cp.async.wait_group 1;" ::: "memory")
#define CP_WAIT0()  asm volatile("cp.async.wait_group 0;" ::: "memory")

__device__ __forceinline__ void mma_f16(float c[4], const unsigned a[4], const unsigned b[2]) {
    asm volatile(
        "mma.sync.aligned.m16n8k16.row.col.f32.f16.f16.f32 "
        "{%0,%1,%2,%3}, {%4,%5,%6,%7}, {%8,%9}, {%0,%1,%2,%3};"
        : "+f"(c[0]), "+f"(c[1]), "+f"(c[2]), "+f"(c[3])
        : "r"(a[0]), "r"(a[1]), "r"(a[2]), "r"(a[3]), "r"(b[0]), "r"(b[1]));
}
__device__ __forceinline__ void ldsm_x4(unsigned r[4], uint32_t addr) {
    asm volatile("ldmatrix.sync.aligned.m8n8.x4.shared.b16 {%0,%1,%2,%3}, [%4];"
        : "=r"(r[0]), "=r"(r[1]), "=r"(r[2]), "=r"(r[3]) : "r"(addr));
}
__device__ __forceinline__ unsigned pack_h2(float a, float b) {
    __half2 h = __floats2half2_rn(a, b);
    return *(unsigned*)&h;
}

// window-layout row -> token index (cyclic shift by +3 both axes)
__device__ __forceinline__ size_t win_row_to_token(int r) {
    int win = r / 49;
    int n   = r - win * 49;
    int b   = win >> 6;
    int wi  = win & 63;
    int ri  = n / 7;
    int ci  = n - ri * 7;
    int hs = (wi >> 3) * 7 + ri + 3; if (hs >= 56) hs -= 56;
    int ws = (wi & 7)  * 7 + ci + 3; if (ws >= 56) ws -= 56;
    return (size_t)b * 3136 + (size_t)hs * 56 + ws;
}

// ---------------- all-weights fp32 -> interleaved fp16 (single launch) ----------------
__global__ __launch_bounds__(256)
void w2h_all(const float* __restrict__ qkv_w, const float* __restrict__ proj_w,
             const float* __restrict__ fc1_w, const float* __restrict__ fc2_w,
             __half2* __restrict__ out) {
    int i = blockIdx.x * 256 + threadIdx.x;
    if (i >= W_TOT) return;
    const float* w; int N, base;
    if      (i < W_PROJ) { w = qkv_w;  N = QKV3;   base = W_QKV;  }
    else if (i < W_FC1)  { w = proj_w; N = CDIM;   base = W_PROJ; }
    else if (i < W_FC2)  { w = fc1_w;  N = HIDDEN; base = W_FC1;  }
    else                 { w = fc2_w;  N = CDIM;   base = W_FC2;  }
    int j = i - base;
    int kq = j / N, n = j - kq * N;
    out[i] = __halves2half2(__float2half(w[(size_t)(2 * kq) * N + n]),
                            __float2half(w[(size_t)(2 * kq + 1) * N + n]));
}

// ---------------- bias+mask table precompute (padded rows of 50) ----------------
__global__ __launch_bounds__(256)
void bias_tbl(const float* __restrict__ rpb, float* __restrict__ tbl) {
    int idx = blockIdx.x * 256 + threadIdx.x;
    if (idx >= BTAB_N) return;
    int cls  = idx / (6 * 49 * BROW);
    int rem  = idx - cls * 6 * 49 * BROW;
    int head = rem / (49 * BROW);
    int e    = rem - head * 49 * BROW;
    int i = e / BROW, j = e - i * BROW;
    if (j >= 49) { tbl[idx] = -1e30f; return; }
    int yi = i / 7, xi = i - yi * 7;
    int yj = j / 7, xj = j - yj * 7;
    float v = rpb[((yi - yj + 6) * 13 + (xi - xj + 6)) * 6 + head];
    bool wy7 = (cls & 2) != 0, wx7 = (cls & 1) != 0;
    int gri = wy7 ? (yi < 4 ? 1 : 2) : 0;
    int gci = wx7 ? (xi < 4 ? 1 : 2) : 0;
    int grj = wy7 ? (yj < 4 ? 1 : 2) : 0;
    int gcj = wx7 ? (xj < 4 ? 1 : 2) : 0;
    if (gri * 3 + gci != grj * 3 + gcj) v -= 100.f;
    tbl[idx] = v;
}

// ---------------- LayerNorm (1 warp per row), fp16 output ----------------
template<bool GATHER>
__global__ __launch_bounds__(256)
void ln_kernel(const float* __restrict__ in, const float* __restrict__ gamma,
               const float* __restrict__ beta, __half* __restrict__ out) {
    int row  = blockIdx.x * 8 + (threadIdx.x >> 5);
    int lane = threadIdx.x & 31;
    size_t t = GATHER ? win_row_to_token(row) : (size_t)row;
    const float* p = in + t * CDIM;
    float v[6];
    float s = 0.f, ss = 0.f;
#pragma unroll
    for (int i = 0; i < 6; i++) {
        v[i] = p[lane + 32 * i];
        s  += v[i];
        ss += v[i] * v[i];
    }
#pragma unroll
    for (int o = 16; o; o >>= 1) {
        s  += __shfl_xor_sync(0xffffffffu, s, o);
        ss += __shfl_xor_sync(0xffffffffu, ss, o);
    }
    float mu   = s * (1.f / CDIM);
    float var  = ss * (1.f / CDIM) - mu * mu;
    float rinv = rsqrtf(var + 1e-5f);
    __half* q = out + (size_t)row * CDIM;
#pragma unroll
    for (int i = 0; i < 6; i++) {
        int c = lane + 32 * i;
        q[c] = __float2half((v[i] - mu) * rinv * gamma[c] + beta[c]);
    }
}

// ---------------- fp16 mma.sync GEMM (R13 config), single barrier per k-iter ----------
// MODE 0: Ch = A@B + bias                      (qkv, fp16 out)
// MODE 1: d_out[token] = x[token] + A@B + bias (proj + window-reverse + residual, fp32)
// MODE 2: Ch = gelu(A@B + bias)                (fc1, fp16 out)
// MODE 3: Cf += A@B + bias                     (fc2 + residual into d_out, fp32)
template<int MODE>
__global__ __launch_bounds__(128, 4)
void gemm_f16(const __half* __restrict__ A, const __half2* __restrict__ Bw,
              const float* __restrict__ bias, void* __restrict__ Cv,
              const float* __restrict__ extra, int K, int N) {
    extern __shared__ __align__(16) char smem[];

    const int tid  = threadIdx.x;
    const int warp = tid >> 5;
    const int lane = tid & 31;
    const int row0 = blockIdx.y * TM;
    const int col0 = blockIdx.x * TN;
    const int wm = (warp & 1) * 64;
    const int wn = (warp >> 1) * 32;
    const int g  = lane >> 2;
    const int tq = lane & 3;
    const int nk = K >> 5;
    const uint32_t sm_u = smem_u32(smem);
    const uint32_t lm_lane = (uint32_t)(((wm + (lane & 15)) * A_PITCH + ((lane >> 4) * 8)) * 2);

    auto issue = [&](int kb, int s) {
        uint32_t st = sm_u + (uint32_t)s * STAGE_BYTES;
        const __half* Abase = A + (size_t)row0 * K + kb * 32;
#pragma unroll
        for (int u = 0; u < 4; u++) {
            int idx = tid + u * 128;
            int m = idx >> 2, c = idx & 3;
            cpa16(st + (uint32_t)(m * A_PITCH + c * 8) * 2, Abase + (size_t)m * K + c * 8);
        }
        uint32_t bt = st + ASZ_H * 2;
        const __half2* Bbase = Bw + (size_t)(kb * 16) * N + col0;
#pragma unroll
        for (int u = 0; u < 2; u++) {
            int idx = tid + u * 128;
            int kq = idx >> 4, c = idx & 15;
            cpa16(bt + (uint32_t)(kq * B_PITCH + c * 4) * 4, Bbase + (size_t)kq * N + c * 4);
        }
    };

    float acc[4][4][4];
#pragma unroll
    for (int mi = 0; mi < 4; mi++)
#pragma unroll
        for (int ni = 0; ni < 4; ni++)
#pragma unroll
            for (int j = 0; j < 4; j++) acc[mi][ni][j] = 0.f;

    issue(0, 0); CP_COMMIT();
    issue(1, 1); CP_COMMIT();

    for (int kb = 0; kb < nk; kb++) {
        if (kb + 2 < nk) { CP_WAIT1(); } else { CP_WAIT0(); }
        __syncthreads();   // single barrier per iteration: orders stage reuse + visibility
        int s = kb % NSTAGE;
        if (kb + 2 < nk) { issue(kb + 2, (kb + 2) % NSTAGE); CP_COMMIT(); }

        uint32_t a_u = sm_u + (uint32_t)s * STAGE_BYTES + lm_lane;
        const __half2* b = (const __half2*)(smem + (size_t)s * STAGE_BYTES + ASZ_H * 2);
#pragma unroll
        for (int ks = 0; ks < 2; ks++) {
            unsigned af[4][4], bf[4][2];
#pragma unroll
            for (int mi = 0; mi < 4; mi++)
                ldsm_x4(af[mi], a_u + (uint32_t)((mi * 16 * A_PITCH + ks * 16) * 2));
#pragma unroll
            for (int ni = 0; ni < 4; ni++) {
                int n0 = wn + ni * 8;
                bf[ni][0] = *(const unsigned*)(b + (ks * 8 + tq)     * B_PITCH + n0 + g);
                bf[ni][1] = *(const unsigned*)(b + (ks * 8 + tq + 4) * B_PITCH + n0 + g);
            }
#pragma unroll
            for (int mi = 0; mi < 4; mi++)
#pragma unroll
                for (int ni = 0; ni < 4; ni++)
                    mma_f16(acc[mi][ni], af[mi], bf[ni]);
        }
    }

    float* Cf = (float*)Cv;
    __half* Ch = (__half*)Cv;
#pragma unroll
    for (int mi = 0; mi < 4; mi++) {
#pragma unroll
        for (int h = 0; h < 2; h++) {
            int r = row0 + wm + mi * 16 + g + h * 8;
            float* dstf = nullptr;
            const float* xrow = nullptr;
            if (MODE == 1) {
                size_t t = win_row_to_token(r);
                dstf = Cf + t * CDIM;
                xrow = extra + t * CDIM;
            } else if (MODE == 3) {
                dstf = Cf + (size_t)r * N;
            }
#pragma unroll
            for (int ni = 0; ni < 4; ni++) {
                int c = col0 + wn + ni * 8 + tq * 2;
                float ox = acc[mi][ni][h * 2 + 0] + bias[c];
                float oy = acc[mi][ni][h * 2 + 1] + bias[c + 1];
                if (MODE == 0) {
                    *(__half2*)(Ch + (size_t)r * N + c) =
                        __halves2half2(__float2half(ox), __float2half(oy));
                } else if (MODE == 1) {
                    float2 xv = *(const float2*)(xrow + c);
                    float2 o = {ox + xv.x, oy + xv.y};
                    *(float2*)(dstf + c) = o;
                } else if (MODE == 2) {
                    ox = 0.5f * ox * (1.f + erff(ox * 0.70710678118654752f));
                    oy = 0.5f * oy * (1.f + erff(oy * 0.70710678118654752f));
                    *(__half2*)(Ch + (size_t)r * N + c) =
                        __halves2half2(__float2half(ox), __float2half(oy));
                } else {
                    float2 cv = *(const float2*)(dstf + c);
                    float2 o = {ox + cv.x, oy + cv.y};
                    *(float2*)(dstf + c) = o;
                }
            }
        }
    }
}

// ---------------- tensor-core windowed attention: global bias table via L2 ------------
#define QK_PITCH 40     // halves per Q/K row
#define VT_PITCH 72     // halves per Vt row
__global__ __launch_bounds__(128)
void attn_tc(const __half* __restrict__ qkv, const float* __restrict__ btab,
             __half* __restrict__ outp) {
    __shared__ __align__(16) __half sQ[64 * QK_PITCH];    // 320 uint4
    __shared__ __align__(16) __half sK[64 * QK_PITCH];    // 320 uint4
    __shared__ __align__(16) __half sVt[32 * VT_PITCH];   // 288 uint4

    const int blk = blockIdx.x;
    const int win = blk / 6, head = blk % 6;
    const int tid = threadIdx.x, warp = tid >> 5, lane = tid & 31;
    const int g = lane >> 2, tq = lane & 3;

    {
        uint4 z4 = {0, 0, 0, 0};
        uint4* zq = (uint4*)sQ;
        uint4* zk = (uint4*)sK;
        uint4* zv = (uint4*)sVt;
#pragma unroll
        for (int u = 0; u < 2; u++) { zq[tid + u * 128] = z4; zk[tid + u * 128] = z4; zv[tid + u * 128] = z4; }
        if (tid < 64) { zq[tid + 256] = z4; zk[tid + 256] = z4; }
        if (tid < 32) zv[tid + 256] = z4;
    }
    __syncthreads();

    const __half* base = qkv + (size_t)win * 49 * QKV3 + head * 32;
    for (int t = tid; t < 49 * 4; t += 128) {
        int n = t >> 2, c = t & 3;
        *(uint4*)(sQ + n * QK_PITCH + c * 8) = *(const uint4*)(base + (size_t)n * QKV3 + c * 8);
        *(uint4*)(sK + n * QK_PITCH + c * 8) = *(const uint4*)(base + (size_t)n * QKV3 + 192 + c * 8);
    }
    for (int t = tid; t < 49 * 16; t += 128) {
        int j = t >> 4, dp = t & 15;
        __half2 h = *(const __half2*)(base + (size_t)j * QKV3 + 384 + dp * 2);
        sVt[(dp * 2)     * VT_PITCH + j] = __low2half(h);
        sVt[(dp * 2 + 1) * VT_PITCH + j] = __high2half(h);
    }
    __syncthreads();

    // ---- QK^T: per warp rows wm..wm+15 ----
    const int wm = warp * 16;
    unsigned aq[2][4];
    {
        uint32_t a_u = smem_u32(sQ) + (uint32_t)(((wm + (lane & 15)) * QK_PITCH + (lane >> 4) * 8) * 2);
        ldsm_x4(aq[0], a_u);
        ldsm_x4(aq[1], a_u + 32);
    }
    float sc[8][4];
#pragma unroll
    for (int nt = 0; nt < 8; nt++) {
        sc[nt][0] = sc[nt][1] = sc[nt][2] = sc[nt][3] = 0.f;
        const __half* kr = sK + (nt * 8 + g) * QK_PITCH + tq * 2;
        unsigned bfa[2] = { *(const unsigned*)kr,        *(const unsigned*)(kr + 8)  };
        unsigned bfb[2] = { *(const unsigned*)(kr + 16), *(const unsigned*)(kr + 24) };
        mma_f16(sc[nt], aq[0], bfa);
        mma_f16(sc[nt], aq[1], bfb);
    }

    // ---- softmax in registers; bias+mask from padded global table (L2-hot) ----
    const int wi = win & 63;
    const int cls = (((wi >> 3) == 7) ? 2 : 0) | (((wi & 7) == 7) ? 1 : 0);
    const float* tb = btab + (size_t)(cls * 6 + head) * 49 * BROW;
    bool rowok[2];
    const float* trow[2];
#pragma unroll
    for (int r = 0; r < 2; r++) {
        int i = wm + g + r * 8;
        rowok[r] = (i < 49);
        trow[r] = tb + (rowok[r] ? i : 0) * BROW + tq * 2;
    }
    const float SCALE = 0.17677669529663687f;
    float vmax[2] = {-1e30f, -1e30f};
#pragma unroll
    for (int nt = 0; nt < 8; nt++) {
        int j0 = nt * 8 + tq * 2;
        float2 t0 = *(const float2*)(trow[0] + nt * 8);
        float2 t1 = *(const float2*)(trow[1] + nt * 8);
        float v0 = (j0     < 49 && rowok[0]) ? fmaf(sc[nt][0], SCALE, t0.x) : -1e30f;
        float v1 = (j0 + 1 < 49 && rowok[0]) ? fmaf(sc[nt][1], SCALE, t0.y) : -1e30f;
        float v2 = (j0     < 49 && rowok[1]) ? fmaf(sc[nt][2], SCALE, t1.x) : -1e30f;
        float v3 = (j0 + 1 < 49 && rowok[1]) ? fmaf(sc[nt][3], SCALE, t1.y) : -1e30f;
        sc[nt][0] = v0; sc[nt][1] = v1; sc[nt][2] = v2; sc[nt][3] = v3;
        vmax[0] = fmaxf(vmax[0], fmaxf(v0, v1));
        vmax[1] = fmaxf(vmax[1], fmaxf(v2, v3));
    }
#pragma unroll
    for (int r = 0; r < 2; r++) {
        vmax[r] = fmaxf(vmax[r], __shfl_xor_sync(0xffffffffu, vmax[r], 1));
        vmax[r] = fmaxf(vmax[r], __shfl_xor_sync(0xffffffffu, vmax[r], 2));
    }
    float vsum[2] = {0.f, 0.f};
#pragma unroll
    for (int nt = 0; nt < 8; nt++) {
#pragma unroll
        for (int c = 0; c < 4; c++) {
            int r = c >> 1;
            float e = __expf(sc[nt][c] - vmax[r]);
            sc[nt][c] = e;
            vsum[r] += e;
        }
    }
#pragma unroll
    for (int r = 0; r < 2; r++) {
        vsum[r] += __shfl_xor_sync(0xffffffffu, vsum[r], 1);
        vsum[r] += __shfl_xor_sync(0xffffffffu, vsum[r], 2);
    }
    float inv0 = 1.f / vsum[0], inv1 = 1.f / vsum[1];

    // ---- P as A-fragments, PV ----
    unsigned ap[4][4];
#pragma unroll
    for (int kc = 0; kc < 4; kc++) {
        ap[kc][0] = pack_h2(sc[2 * kc][0],     sc[2 * kc][1]);
        ap[kc][1] = pack_h2(sc[2 * kc][2],     sc[2 * kc][3]);
        ap[kc][2] = pack_h2(sc[2 * kc + 1][0], sc[2 * kc + 1][1]);
        ap[kc][3] = pack_h2(sc[2 * kc + 1][2], sc[2 * kc + 1][3]);
    }
    float oacc[4][4];
#pragma unroll
    for (int dt = 0; dt < 4; dt++) {
        oacc[dt][0] = oacc[dt][1] = oacc[dt][2] = oacc[dt][3] = 0.f;
#pragma unroll
        for (int kc = 0; kc < 4; kc++) {
            const __half* vr = sVt + (dt * 8 + g) * VT_PITCH + kc * 16 + tq * 2;
            unsigned bf[2] = { *(const unsigned*)vr, *(const unsigned*)(vr + 8) };
            mma_f16(oacc[dt], ap[kc], bf);
        }
    }

    // ---- store ----
#pragma unroll
    for (int r = 0; r < 2; r++) {
        int i = wm + g + r * 8;
        if (i < 49) {
            float invr = r ? inv1 : inv0;
            __half* dst = outp + ((size_t)win * 49 + i) * CDIM + head * 32;
#pragma unroll
            for (int dt = 0; dt < 4; dt++) {
                float ox = oacc[dt][r * 2 + 0] * invr;
                float oy = oacc[dt][r * 2 + 1] * invr;
                *(__half2*)(dst + dt * 8 + tq * 2) = __floats2half2_rn(ox, oy);
            }
        }
    }
}

// ---------------- launch ----------------
extern "C" void kernel_launch(void* const* d_in, const int* in_sizes, int n_in,
                              void* d_out, int out_size) {
    const float* x      = (const float*)d_in[0];
    const float* n1g    = (const float*)d_in[1];
    const float* n1b    = (const float*)d_in[2];
    const float* qkv_w  = (const float*)d_in[3];
    const float* qkv_b  = (const float*)d_in[4];
    const float* rpb    = (const float*)d_in[5];
    const float* proj_w = (const float*)d_in[6];
    const float* proj_b = (const float*)d_in[7];
    const float* n2g    = (const float*)d_in[8];
    const float* n2b    = (const float*)d_in[9];
    const float* fc1_w  = (const float*)d_in[10];
    const float* fc1_b  = (const float*)d_in[11];
    const float* fc2_w  = (const float*)d_in[12];
    const float* fc2_b  = (const float*)d_in[13];
    float* out = (float*)d_out;

    __half *p_xw, *p_qkv, *p_attn, *p_y, *p_h;
    __half2 *p_w16;
    float *p_btab;
    cudaGetSymbolAddress((void**)&p_xw,   g_xw);
    cudaGetSymbolAddress((void**)&p_qkv,  g_qkv);
    cudaGetSymbolAddress((void**)&p_attn, g_attn);
    cudaGetSymbolAddress((void**)&p_y,    g_y);
    cudaGetSymbolAddress((void**)&p_h,    g_h);
    cudaGetSymbolAddress((void**)&p_w16,  g_w16);
    cudaGetSymbolAddress((void**)&p_btab, g_btab);

    cudaFuncSetAttribute(gemm_f16<0>, cudaFuncAttributeMaxDynamicSharedMemorySize, SMEM_SZ);
    cudaFuncSetAttribute(gemm_f16<1>, cudaFuncAttributeMaxDynamicSharedMemorySize, SMEM_SZ);
    cudaFuncSetAttribute(gemm_f16<2>, cudaFuncAttributeMaxDynamicSharedMemorySize, SMEM_SZ);
    cudaFuncSetAttribute(gemm_f16<3>, cudaFuncAttributeMaxDynamicSharedMemorySize, SMEM_SZ);

    const int MT = M_ROWS / TM;   // 784

    // 0. weight conversion + bias table (global, L2-hot)
    w2h_all<<<(W_TOT + 255) / 256, 256>>>(qkv_w, proj_w, fc1_w, fc2_w, p_w16);
    bias_tbl<<<(BTAB_N + 255) / 256, 256>>>(rpb, p_btab);

    // 1. LN1 + shift + window partition (fp16 out)
    ln_kernel<true><<<M_ROWS / 8, 256>>>(x, n1g, n1b, p_xw);
    // 2. QKV projection (fp16 out)
    gemm_f16<0><<<dim3(QKV3 / TN, MT), 128, SMEM_SZ>>>(p_xw, p_w16 + W_QKV, qkv_b, p_qkv, nullptr, CDIM, QKV3);
    // 3. tensor-core windowed attention (fp16 in/out)
    attn_tc<<<2048 * 6, 128>>>(p_qkv, p_btab, p_attn);
    // 4. proj + window reverse + un-shift + residual -> d_out holds x1 (fp32)
    gemm_f16<1><<<dim3(CDIM / TN, MT), 128, SMEM_SZ>>>(p_attn, p_w16 + W_PROJ, proj_b, out, x, CDIM, CDIM);
    // 5. LN2 (fp16 out)
    ln_kernel<false><<<M_ROWS / 8, 256>>>(out, n2g, n2b, p_y);
    // 6. FC1 + GELU (fp16 out)
    gemm_f16<2><<<dim3(HIDDEN / TN, MT), 128, SMEM_SZ>>>(p_y, p_w16 + W_FC1, fc1_b, p_h, nullptr, CDIM, HIDDEN);
    // 7. FC2 + residual add into d_out (fp32)
    gemm_f16<3><<<dim3(CDIM / TN, MT), 128, SMEM_SZ>>>(p_h, p_w16 + W_FC2, fc2_b, out, nullptr, HIDDEN, CDIM);
}